// round 16
// baseline (speedup 1.0000x reference)
#include <cuda_runtime.h>
#include <cuda_bf16.h>

// out[b,t,c] = (x[b,src,c] + noise[b,src,c]*0.1f) * scale[b]
// src = (t - (shifts[b] - MAX_SHIFT)) mod T
// B=64, T=4096, C=128, fp32.
//
// Store-policy probe: ld.cs reads + st.wt WRITE-THROUGH store (no L2 dirty
// line allocation at all; write data flows straight to DRAM write queues).
// Policy map (sustained): none/none=61.50, cs/none=63.71, none/cs=61.50,
// cg/cs=61.63, cs/cs=59.87 (banked best, reproduced 4x). This tests whether
// removing write-allocate entirely beats evict-first writes.

#define B_DIM 64
#define T_DIM 4096
#define C_DIM 128
#define MAX_SHIFT 409
#define NOISE_STD 0.1f

#define C4 (C_DIM / 4)   // 32 float4 per (b,t) row
#define THREADS 256

__global__ __launch_bounds__(THREADS)
void ts_augment_kernel(const float4* __restrict__ x,
                       const float4* __restrict__ noise,
                       const float*  __restrict__ scale,
                       const int*    __restrict__ shifts,
                       float4*       __restrict__ out)
{
    // flat index over B * T * C4 = 8,388,608; grid*block covers exactly.
    unsigned idx = blockIdx.x * blockDim.x + threadIdx.x;
    unsigned c4 = idx & (C4 - 1);            // idx % 32
    unsigned t  = (idx >> 5) & (T_DIM - 1);  // (idx / 32) % 4096
    unsigned b  = idx >> 17;                 // idx / (32*4096)

    int s = shifts[b] - MAX_SHIFT;           // [-409, 409]
    int src = (int)t - s;                    // [-409, 4504]
    if (src < 0)           src += T_DIM;
    else if (src >= T_DIM) src -= T_DIM;

    unsigned src_idx = (b << 17) + ((unsigned)src << 5) + c4;

    // Evict-first reads (established good with a streaming write side).
    float4 xv = __ldcs(&x[src_idx]);
    float4 nv = __ldcs(&noise[src_idx]);

    float sc  = __ldg(&scale[b]);
    float nsc = sc * NOISE_STD;   // out = x*sc + n*(0.1*sc): independent MUL + FMA per lane

    float4 o;
    o.x = fmaf(nv.x, nsc, xv.x * sc);
    o.y = fmaf(nv.y, nsc, xv.y * sc);
    o.z = fmaf(nv.z, nsc, xv.z * sc);
    o.w = fmaf(nv.w, nsc, xv.w * sc);

    // Write-through store: no L2 dirty-line allocation for the output stream.
    __stwt(&out[idx], o);
}

extern "C" void kernel_launch(void* const* d_in, const int* in_sizes, int n_in,
                              void* d_out, int out_size)
{
    const float4* x      = (const float4*)d_in[0];
    const float4* noise  = (const float4*)d_in[1];
    const float*  scale  = (const float*)d_in[2];
    const int*    shifts = (const int*)d_in[3];
    float4* out = (float4*)d_out;

    const unsigned total = B_DIM * T_DIM * C4;   // 8,388,608
    const unsigned blocks = total / THREADS;     // 32768

    ts_augment_kernel<<<blocks, THREADS>>>(x, noise, scale, shifts, out);
}

// round 17
// speedup vs baseline: 1.0076x; 1.0076x over previous
#include <cuda_runtime.h>
#include <cuda_bf16.h>

// out[b,t,c] = (x[b,src,c] + noise[b,src,c]*0.1f) * scale[b]
// src = (t - (shifts[b] - MAX_SHIFT)) mod T
// B=64, T=4096, C=128, fp32.
//
// FINAL kernel — measured-optimal configuration, reproduced 4x at
// 59.87-60.00 us sustained (graph-replay bench):
//   * float4 (128-bit) accesses     (v8=61.95, batched-ILP worse)
//   * 256-thread blocks             (128/512 -> 61.09/61.50; convex)
//   * ld.cs + st.cs                 (strict interior optimum of the policy
//                                    lattice: none/none=61.50, cs/none=63.71,
//                                    none/cs=61.50, cg/cs=61.63, cs/wt=63.55)
//   * hoisted per-batch scale, MUL+FMA per lane, regs=22, occ~80%
// ~6.4 TB/s sustained on an irreducible 384 MB touch-once 2R:1W stream
// (compulsory-traffic floor at 8 TB/s spec = 50 us).

#define B_DIM 64
#define T_DIM 4096
#define C_DIM 128
#define MAX_SHIFT 409
#define NOISE_STD 0.1f

#define C4 (C_DIM / 4)   // 32 float4 per (b,t) row
#define THREADS 256

__global__ __launch_bounds__(THREADS)
void ts_augment_kernel(const float4* __restrict__ x,
                       const float4* __restrict__ noise,
                       const float*  __restrict__ scale,
                       const int*    __restrict__ shifts,
                       float4*       __restrict__ out)
{
    // flat index over B * T * C4 = 8,388,608; grid*block covers exactly.
    unsigned idx = blockIdx.x * blockDim.x + threadIdx.x;
    unsigned c4 = idx & (C4 - 1);            // idx % 32
    unsigned t  = (idx >> 5) & (T_DIM - 1);  // (idx / 32) % 4096
    unsigned b  = idx >> 17;                 // idx / (32*4096)

    int s = shifts[b] - MAX_SHIFT;           // [-409, 409]
    int src = (int)t - s;                    // [-409, 4504]
    if (src < 0)           src += T_DIM;
    else if (src >= T_DIM) src -= T_DIM;

    unsigned src_idx = (b << 17) + ((unsigned)src << 5) + c4;

    // Touch-once streams: evict-first reads + streaming store (the policy
    // PAIR is what wins; each alone is neutral-to-harmful).
    float4 xv = __ldcs(&x[src_idx]);
    float4 nv = __ldcs(&noise[src_idx]);

    float sc  = __ldg(&scale[b]);
    float nsc = sc * NOISE_STD;   // out = x*sc + n*(0.1*sc): independent MUL + FMA per lane

    float4 o;
    o.x = fmaf(nv.x, nsc, xv.x * sc);
    o.y = fmaf(nv.y, nsc, xv.y * sc);
    o.z = fmaf(nv.z, nsc, xv.z * sc);
    o.w = fmaf(nv.w, nsc, xv.w * sc);

    __stcs(&out[idx], o);
}

extern "C" void kernel_launch(void* const* d_in, const int* in_sizes, int n_in,
                              void* d_out, int out_size)
{
    const float4* x      = (const float4*)d_in[0];
    const float4* noise  = (const float4*)d_in[1];
    const float*  scale  = (const float*)d_in[2];
    const int*    shifts = (const int*)d_in[3];
    float4* out = (float4*)d_out;

    const unsigned total = B_DIM * T_DIM * C4;   // 8,388,608
    const unsigned blocks = total / THREADS;     // 32768

    ts_augment_kernel<<<blocks, THREADS>>>(x, noise, scale, shifts, out);
}